// round 12
// baseline (speedup 1.0000x reference)
#include <cuda_runtime.h>

#define N_B   64
#define T_N   1024
#define SIGD  780
#define M_TOT (N_B * T_N)   // 65536

// 204 MB scratch for the signature stream c[n][t][sig]
__device__ float g_c[(size_t)N_B * T_N * SIGD];

// ---------------------------------------------------------------------------
// Kernel 1: pointwise conv (k=1) + streamed truncated signature (depth 4).
// One CTA per batch element; 256 threads cover the 780 signature coordinates.
// Level 1-3 state (155 floats) lives in shared; level-4 state in registers.
// ---------------------------------------------------------------------------
__global__ __launch_bounds__(256) void sig_kernel(
    const float* __restrict__ batch,    // [64][1024][4]
    const float* __restrict__ conv_w,   // [5][5]
    const float* __restrict__ conv_b)   // [5]
{
    const int n   = blockIdx.x;
    const int tid = threadIdx.x;

    __shared__ float sW[25];
    __shared__ float sB[5];
    __shared__ float sd[5];     // current increment d (post-conv)
    __shared__ float sS[155];   // signature levels 1..3 (old values)

    if (tid < 25)  sW[tid] = conv_w[tid];
    if (tid < 5)   sB[tid] = conv_b[tid];
    if (tid < 155) sS[tid] = 0.f;

    float Sreg[4] = {0.f, 0.f, 0.f, 0.f};   // per-thread signature state

    // pipelined batch-row registers (only threads 0..4 use them)
    float4 pv = make_float4(0.f, 0.f, 0.f, 0.f);
    float4 cv = make_float4(0.f, 0.f, 0.f, 0.f);
    if (tid < 5)
        cv = *reinterpret_cast<const float4*>(batch + (size_t)n * T_N * 4);

    __syncthreads();

    float* crow = g_c + (size_t)n * T_N * SIGD;

    for (int t = 0; t < T_N; ++t) {
        // --- phase 1: threads 0..4 compute d_j = conv_w[j,:] @ delta_a ---
        if (tid < 5) {
            float4 nv = cv;
            if (t + 1 < T_N)
                nv = *reinterpret_cast<const float4*>(
                        batch + ((size_t)n * T_N + t + 1) * 4);
            float dd = sW[tid*5+0]*(cv.x - pv.x)
                     + sW[tid*5+1]*(cv.y - pv.y)
                     + sW[tid*5+2]*(cv.z - pv.z)
                     + sW[tid*5+3]*(cv.w - pv.w)
                     + sW[tid*5+4]*(1.f/1024.f);   // time-channel increment
            if (t == 0) dd += sB[tid];             // first increment = b[0] - 0
            sd[tid] = dd;
            pv = cv; cv = nv;
        }
        __syncthreads();

        // --- phase 2: each thread computes its new signature values ---
        float nvv[4];
#pragma unroll
        for (int s = 0; s < 4; ++s) {
            int idx = tid + s * 256;
            if (idx < SIGD) {
                float S = Sreg[s];
                float v;
                if (idx < 5) {
                    v = S + sd[idx];
                } else if (idx < 30) {
                    int l = idx - 5; int i1 = l / 5, i2 = l % 5;
                    v = S + sd[i2] * (0.5f * sd[i1] + sS[i1]);
                } else if (idx < 155) {
                    int l = idx - 30;
                    int i1 = l / 25; int r = l % 25; int i2 = r / 5, i3 = r % 5;
                    float d3  = sd[i3];
                    float d23 = sd[i2] * d3;
                    v = S + d23 * ((1.f/6.f) * sd[i1] + 0.5f * sS[i1])
                          + sS[5 + l/5] * d3;
                } else {
                    int l = idx - 155;
                    int i1 = l / 125; int r = l % 125;
                    int i2 = r / 25;  int r2 = r % 25;
                    int i3 = r2 / 5,  i4 = r2 % 5;
                    float d4   = sd[i4];
                    float d34  = sd[i3] * d4;
                    float d234 = sd[i2] * d34;
                    v = S + d234 * ((1.f/24.f) * sd[i1] + (1.f/6.f) * sS[i1])
                          + 0.5f * sS[5 + l/25] * d34
                          + sS[30 + l/5] * d4;
                }
                nvv[s] = v;
            }
        }
        __syncthreads();

        // --- phase 3: commit state + stream output (t==0 row is zeroed) ---
#pragma unroll
        for (int s = 0; s < 4; ++s) {
            int idx = tid + s * 256;
            if (idx < SIGD) {
                Sreg[s] = nvv[s];
                if (idx < 155) sS[idx] = nvv[s];
                crow[idx] = (t == 0) ? 0.f : nvv[s];
            }
        }
        crow += SIGD;
    }
}

// ---------------------------------------------------------------------------
// Kernel 2: out[m][j] = tanh( sum_k c[m][k] * lin_w[j][k] + lin_b[j] )
// M=65536, N=780, K=780. 128x128x8 tiles, 8x8 micro-tile per thread,
// accumulation via packed fma.rn.f32x2 (2 fp32 FMAs/instr on sm_103a).
// ---------------------------------------------------------------------------
__device__ __forceinline__ unsigned long long dup2(float x) {
    unsigned long long r;
    asm("mov.b64 %0, {%1, %1};" : "=l"(r) : "f"(x));
    return r;
}
__device__ __forceinline__ void fma2(unsigned long long& d,
                                     unsigned long long a,
                                     unsigned long long b) {
    asm("fma.rn.f32x2 %0, %1, %2, %0;" : "+l"(d) : "l"(a), "l"(b));
}

#define BM 128
#define BN 128
#define BKD 8

__global__ __launch_bounds__(256, 2) void gemm_tanh_kernel(
    const float* __restrict__ lin_w,   // [780][780] row-major (j, k)
    const float* __restrict__ lin_b,   // [780]
    float* __restrict__ out)           // [65536][780]
{
    __shared__ float As[BKD][BM];
    __shared__ float Bs[BKD][BN];

    const int tid = threadIdx.x;
    const int tx  = tid & 15;          // 16 threads over N
    const int ty  = tid >> 4;          // 16 threads over M
    const int mBase = blockIdx.y * BM;
    const int nBase = blockIdx.x * BN;

    const int lrow = tid >> 1;          // 0..127 tile row for loads
    const int lkq  = (tid & 1) * 4;     // k sub-offset 0 or 4

    const float* Arow = g_c + (size_t)(mBase + lrow) * SIGD;
    const int jrow = nBase + lrow;
    const float* Wrow = lin_w + (size_t)jrow * SIGD;
    const bool jvalid = (jrow < SIGD);

    unsigned long long acc[8][4];
#pragma unroll
    for (int i = 0; i < 8; ++i)
#pragma unroll
        for (int j = 0; j < 4; ++j) acc[i][j] = 0ull;

    for (int kt = 0; kt < SIGD; kt += BKD) {
        const int k = kt + lkq;
        float4 av = make_float4(0.f,0.f,0.f,0.f);
        float4 bv = make_float4(0.f,0.f,0.f,0.f);
        if (k < SIGD) {                      // 780 % 4 == 0 -> full float4 valid
            av = *reinterpret_cast<const float4*>(Arow + k);
            if (jvalid)
                bv = *reinterpret_cast<const float4*>(Wrow + k);
        }
        __syncthreads();   // previous compute phase done before overwriting smem
        As[lkq+0][lrow] = av.x; As[lkq+1][lrow] = av.y;
        As[lkq+2][lrow] = av.z; As[lkq+3][lrow] = av.w;
        Bs[lkq+0][lrow] = bv.x; Bs[lkq+1][lrow] = bv.y;
        Bs[lkq+2][lrow] = bv.z; Bs[lkq+3][lrow] = bv.w;
        __syncthreads();

#pragma unroll
        for (int kk = 0; kk < BKD; ++kk) {
            float4 a0 = *reinterpret_cast<const float4*>(&As[kk][ty*8]);
            float4 a1 = *reinterpret_cast<const float4*>(&As[kk][ty*8+4]);
            ulonglong2 bA = *reinterpret_cast<const ulonglong2*>(&Bs[kk][tx*8]);
            ulonglong2 bB = *reinterpret_cast<const ulonglong2*>(&Bs[kk][tx*8+4]);
            float aa[8] = {a0.x,a0.y,a0.z,a0.w,a1.x,a1.y,a1.z,a1.w};
#pragma unroll
            for (int i = 0; i < 8; ++i) {
                unsigned long long ad = dup2(aa[i]);
                fma2(acc[i][0], ad, bA.x);
                fma2(acc[i][1], ad, bA.y);
                fma2(acc[i][2], ad, bB.x);
                fma2(acc[i][3], ad, bB.y);
            }
        }
    }

    // epilogue: unpack pairs, add bias, tanh, predicated store (N tail = 12)
#pragma unroll
    for (int i = 0; i < 8; ++i) {
        const int m = mBase + ty*8 + i;
        float* orow = out + (size_t)m * SIGD;
#pragma unroll
        for (int j = 0; j < 4; ++j) {
            const int col = nBase + tx*8 + j*2;
            float v0 = __uint_as_float((unsigned)(acc[i][j] & 0xffffffffull));
            float v1 = __uint_as_float((unsigned)(acc[i][j] >> 32));
            if (col < SIGD)     orow[col]     = tanhf(v0 + lin_b[col]);
            if (col + 1 < SIGD) orow[col + 1] = tanhf(v1 + lin_b[col + 1]);
        }
    }
}

// ---------------------------------------------------------------------------
// inputs (metadata order): batch, conv_w, conv_b, lin_w, lin_b
// ---------------------------------------------------------------------------
extern "C" void kernel_launch(void* const* d_in, const int* in_sizes, int n_in,
                              void* d_out, int out_size) {
    const float* batch  = (const float*)d_in[0];
    const float* conv_w = (const float*)d_in[1];
    const float* conv_b = (const float*)d_in[2];
    const float* lin_w  = (const float*)d_in[3];
    const float* lin_b  = (const float*)d_in[4];
    float* out = (float*)d_out;

    sig_kernel<<<N_B, 256>>>(batch, conv_w, conv_b);

    dim3 grid((SIGD + BN - 1) / BN, M_TOT / BM);   // (7, 512)
    gemm_tanh_kernel<<<grid, 256>>>(lin_w, lin_b, out);
}

// round 16
// speedup vs baseline: 1.9369x; 1.9369x over previous
#include <cuda_runtime.h>
#include <cuda_bf16.h>
#include <cstdint>

#define N_B   64
#define T_N   1024
#define SIGD  780
#define KPAD  832            // 26 * 32
#define NPAD  896            // 7 * 128
#define M_TOT (N_B * T_N)    // 65536
#define BK    32
#define KITER (KPAD / BK)    // 26
#define NITER (3 * KITER)    // 78: pass0 hi*hi, pass1 hi*lo, pass2 lo*hi

// pre-split bf16 operands (zero-initialized .bss; pads stay zero)
__device__ __align__(1024) __nv_bfloat16 g_chi[(size_t)M_TOT * KPAD];
__device__ __align__(1024) __nv_bfloat16 g_clo[(size_t)M_TOT * KPAD];
__device__ __align__(1024) __nv_bfloat16 g_bhi[(size_t)NPAD * KPAD];
__device__ __align__(1024) __nv_bfloat16 g_blo[(size_t)NPAD * KPAD];

// ---------------------------------------------------------------------------
// helpers
// ---------------------------------------------------------------------------
__device__ __forceinline__ uint32_t smem_u32(const void* p) {
    uint32_t a;
    asm("{ .reg .u64 t; cvta.to.shared.u64 t, %1; cvt.u32.u64 %0, t; }"
        : "=r"(a) : "l"(p));
    return a;
}
__device__ __forceinline__ void cpasync16(uint32_t s, const void* g) {
    asm volatile("cp.async.cg.shared.global [%0], [%1], 16;"
                 :: "r"(s), "l"(g) : "memory");
}
__device__ __forceinline__ void cp_commit() {
    asm volatile("cp.async.commit_group;" ::: "memory");
}
__device__ __forceinline__ void cp_wait0() {
    asm volatile("cp.async.wait_group 0;" ::: "memory");
}
__device__ __forceinline__ void ldsm4(uint32_t* r, uint32_t addr) {
    asm volatile("ldmatrix.sync.aligned.m8n8.x4.shared.b16 {%0,%1,%2,%3}, [%4];"
                 : "=r"(r[0]), "=r"(r[1]), "=r"(r[2]), "=r"(r[3]) : "r"(addr));
}
__device__ __forceinline__ void mma16816(float* c, const uint32_t* a,
                                         uint32_t b0, uint32_t b1) {
    asm volatile(
        "mma.sync.aligned.m16n8k16.row.col.f32.bf16.bf16.f32 "
        "{%0,%1,%2,%3}, {%4,%5,%6,%7}, {%8,%9}, {%0,%1,%2,%3};"
        : "+f"(c[0]), "+f"(c[1]), "+f"(c[2]), "+f"(c[3])
        : "r"(a[0]), "r"(a[1]), "r"(a[2]), "r"(a[3]), "r"(b0), "r"(b1));
}
__device__ __forceinline__ float fast_tanh(float x) {
    float y; asm("tanh.approx.f32 %0, %1;" : "=f"(y) : "f"(x)); return y;
}

// ---------------------------------------------------------------------------
// Kernel 1: conv + streamed signature -> bf16 hi/lo stream (one CTA / batch n)
// ---------------------------------------------------------------------------
__global__ __launch_bounds__(256) void sig_kernel(
    const float* __restrict__ batch,
    const float* __restrict__ conv_w,
    const float* __restrict__ conv_b)
{
    const int n   = blockIdx.x;
    const int tid = threadIdx.x;

    __shared__ float sW[25];
    __shared__ float sB[5];
    __shared__ float sd[T_N * 5];
    __shared__ float sS[2][160];

    if (tid < 25) sW[tid] = conv_w[tid];
    if (tid < 5)  sB[tid] = conv_b[tid];
    if (tid < 160) { sS[0][tid] = 0.f; sS[1][tid] = 0.f; }
    __syncthreads();

    const float4* bb = reinterpret_cast<const float4*>(batch + (size_t)n * T_N * 4);
#pragma unroll
    for (int s = 0; s < 4; ++s) {
        int t = tid + s * 256;
        float4 cv = bb[t];
        float4 pv = (t > 0) ? bb[t - 1] : make_float4(0.f, 0.f, 0.f, 0.f);
        float dx0 = cv.x - pv.x, dx1 = cv.y - pv.y;
        float dx2 = cv.z - pv.z, dx3 = cv.w - pv.w;
#pragma unroll
        for (int j = 0; j < 5; ++j) {
            float dv = sW[j*5+0]*dx0 + sW[j*5+1]*dx1 + sW[j*5+2]*dx2
                     + sW[j*5+3]*dx3 + sW[j*5+4]*(1.f/1024.f);
            if (t == 0) dv += sB[j];
            sd[t*5 + j] = dv;
        }
    }
    __syncthreads();

    float Sreg[4] = {0.f, 0.f, 0.f, 0.f};
    __nv_bfloat16* hrow = g_chi + (size_t)n * T_N * KPAD;
    __nv_bfloat16* lrow = g_clo + (size_t)n * T_N * KPAD;
    int p = 0;

    for (int t = 0; t < T_N; ++t) {
        const float* d  = sd + t * 5;
        const float* So = sS[p];
        float*       Sn = sS[p ^ 1];
#pragma unroll
        for (int s = 0; s < 4; ++s) {
            int idx = tid + s * 256;
            if (idx < SIGD) {
                float S = Sreg[s];
                float v;
                if (idx < 5) {
                    v = S + d[idx];
                } else if (idx < 30) {
                    int l = idx - 5; int i1 = l / 5, i2 = l % 5;
                    v = S + d[i2] * (0.5f * d[i1] + So[i1]);
                } else if (idx < 155) {
                    int l = idx - 30;
                    int i1 = l / 25; int r = l % 25; int i2 = r / 5, i3 = r % 5;
                    float d3  = d[i3];
                    float d23 = d[i2] * d3;
                    v = S + d23 * ((1.f/6.f) * d[i1] + 0.5f * So[i1])
                          + So[5 + l/5] * d3;
                } else {
                    int l = idx - 155;
                    int i1 = l / 125; int r = l % 125;
                    int i2 = r / 25;  int r2 = r % 25;
                    int i3 = r2 / 5,  i4 = r2 % 5;
                    float d4   = d[i4];
                    float d34  = d[i3] * d4;
                    float d234 = d[i2] * d34;
                    v = S + d234 * ((1.f/24.f) * d[i1] + (1.f/6.f) * So[i1])
                          + 0.5f * So[5 + l/25] * d34
                          + So[30 + l/5] * d4;
                }
                Sreg[s] = v;
                if (idx < 155) Sn[idx] = v;
                float vo = (t == 0) ? 0.f : v;
                __nv_bfloat16 h = __float2bfloat16(vo);
                __nv_bfloat16 lo = __float2bfloat16(vo - __bfloat162float(h));
                hrow[idx] = h; lrow[idx] = lo;
            } else if (idx < KPAD) {
                hrow[idx] = __float2bfloat16(0.f);
                lrow[idx] = __float2bfloat16(0.f);
            }
        }
        __syncthreads();
        p ^= 1;
        hrow += KPAD; lrow += KPAD;
    }
}

// ---------------------------------------------------------------------------
// Kernel 2: split lin_w into bf16 hi/lo, padded [896][832]
// ---------------------------------------------------------------------------
__global__ void bsplit_kernel(const float* __restrict__ lin_w) {
    int idx = blockIdx.x * 256 + threadIdx.x;
    if (idx >= NPAD * KPAD) return;
    int nn = idx / KPAD, kk = idx % KPAD;
    float v = (nn < SIGD && kk < SIGD) ? lin_w[nn * SIGD + kk] : 0.f;
    __nv_bfloat16 h = __float2bfloat16(v);
    __nv_bfloat16 lo = __float2bfloat16(v - __bfloat162float(h));
    g_bhi[idx] = h; g_blo[idx] = lo;
}

// ---------------------------------------------------------------------------
// Kernel 3: HMMA (mma.sync bf16) split-bf16 GEMM + bias + tanh
// 128x128x32 CTA tile, 8 warps (2m x 4n), 64x32 warp tile, cp.async 2-stage.
// smem rows padded to 80B -> conflict-free ldmatrix (row*20 mod 32 permutes).
// ---------------------------------------------------------------------------
#define ROWB    80
#define STAGE_B (128 * ROWB)           // 10240 B per operand tile

__device__ __forceinline__ void src_of(int i, const __nv_bfloat16*& pa,
                                       const __nv_bfloat16*& pb, int& kt) {
    int pass = i / KITER; kt = i - pass * KITER;
    pa = (pass < 2) ? g_chi : g_clo;
    pb = (pass == 1) ? g_blo : g_bhi;
}

__global__ __launch_bounds__(256, 2) void gemm_mma(
    const float* __restrict__ lin_b,
    float* __restrict__ out)
{
    __shared__ __align__(128) char sm[2 * 2 * STAGE_B];   // 40 KB

    const int tid = threadIdx.x;
    const int lid = tid & 31, wid = tid >> 5;
    const int wm = wid & 1, wn = wid >> 1;                 // 2 x 4 warp grid
    const int mBase = blockIdx.y * 128;
    const int nBase = blockIdx.x * 128;

    const uint32_t sbase = smem_u32(sm);
    uint32_t sA[2], sB[2];
#pragma unroll
    for (int s = 0; s < 2; ++s) {
        sA[s] = sbase + s * 2 * STAGE_B;
        sB[s] = sA[s] + STAGE_B;
    }

    // ---- loader mapping: thread -> (row, two 16B chunks) ----
    const int lrow = tid >> 1;
    const int lc   = (tid & 1) * 2;                        // chunk 0/2
    const uint32_t stoff = lrow * ROWB + lc * 16;
    const size_t gArow = (size_t)(mBase + lrow) * KPAD + lc * 8;
    const size_t gBrow = (size_t)(nBase + lrow) * KPAD + lc * 8;

    // ---- ldmatrix lane offsets ----
    const int q = lid >> 3, rr = lid & 7;
    const uint32_t aoff = (uint32_t)(wm * 64 + (q & 1) * 8 + rr) * ROWB
                        + (uint32_t)(q >> 1) * 16;
    const uint32_t boff = (uint32_t)(wn * 32 + (q >> 1) * 8 + rr) * ROWB
                        + (uint32_t)(q & 1) * 16;

    float acc[4][4][4];
#pragma unroll
    for (int f = 0; f < 4; ++f)
#pragma unroll
        for (int j = 0; j < 4; ++j)
#pragma unroll
            for (int e = 0; e < 4; ++e) acc[f][j][e] = 0.f;

    // prologue: stage 0
    {
        const __nv_bfloat16 *pa, *pb; int kt;
        src_of(0, pa, pb, kt);
        cpasync16(sA[0] + stoff,      pa + gArow + kt * BK);
        cpasync16(sA[0] + stoff + 16, pa + gArow + kt * BK + 8);
        cpasync16(sB[0] + stoff,      pb + gBrow + kt * BK);
        cpasync16(sB[0] + stoff + 16, pb + gBrow + kt * BK + 8);
        cp_commit();
    }

    for (int i = 0; i < NITER; ++i) {
        cp_wait0();
        __syncthreads();
        if (i + 1 < NITER) {
            const __nv_bfloat16 *pa, *pb; int kt;
            src_of(i + 1, pa, pb, kt);
            const int s = (i + 1) & 1;
            cpasync16(sA[s] + stoff,      pa + gArow + kt * BK);
            cpasync16(sA[s] + stoff + 16, pa + gArow + kt * BK + 8);
            cpasync16(sB[s] + stoff,      pb + gBrow + kt * BK);
            cpasync16(sB[s] + stoff + 16, pb + gBrow + kt * BK + 8);
            cp_commit();
        }

        const int st = i & 1;
#pragma unroll
        for (int s16 = 0; s16 < 2; ++s16) {
            uint32_t a[4][4];
#pragma unroll
            for (int f = 0; f < 4; ++f)
                ldsm4(a[f], sA[st] + aoff + f * 16 * ROWB + s16 * 32);
            uint32_t b[2][4];
#pragma unroll
            for (int g = 0; g < 2; ++g)
                ldsm4(b[g], sB[st] + boff + g * 16 * ROWB + s16 * 32);
#pragma unroll
            for (int f = 0; f < 4; ++f)
#pragma unroll
                for (int j = 0; j < 4; ++j)
                    mma16816(acc[f][j], a[f],
                             b[j >> 1][(j & 1) * 2],
                             b[j >> 1][(j & 1) * 2 + 1]);
        }
    }

    // ---- epilogue: bias + tanh + predicated float2 stores ----
#pragma unroll
    for (int j = 0; j < 4; ++j) {
        const int nn = nBase + wn * 32 + j * 8 + (lid & 3) * 2;
        if (nn < SIGD) {
            const float b0 = lin_b[nn], b1 = lin_b[nn + 1];
#pragma unroll
            for (int f = 0; f < 4; ++f) {
                const int m0 = mBase + wm * 64 + f * 16 + (lid >> 2);
                float2 v0, v1;
                v0.x = fast_tanh(acc[f][j][0] + b0);
                v0.y = fast_tanh(acc[f][j][1] + b1);
                v1.x = fast_tanh(acc[f][j][2] + b0);
                v1.y = fast_tanh(acc[f][j][3] + b1);
                *reinterpret_cast<float2*>(out + (size_t)m0 * SIGD + nn) = v0;
                *reinterpret_cast<float2*>(out + (size_t)(m0 + 8) * SIGD + nn) = v1;
            }
        }
    }
}

// ---------------------------------------------------------------------------
// inputs: batch, conv_w, conv_b, lin_w, lin_b
// ---------------------------------------------------------------------------
extern "C" void kernel_launch(void* const* d_in, const int* in_sizes, int n_in,
                              void* d_out, int out_size) {
    const float* batch  = (const float*)d_in[0];
    const float* conv_w = (const float*)d_in[1];
    const float* conv_b = (const float*)d_in[2];
    const float* lin_w  = (const float*)d_in[3];
    const float* lin_b  = (const float*)d_in[4];
    float* out = (float*)d_out;

    bsplit_kernel<<<(NPAD * KPAD + 255) / 256, 256>>>(lin_w);
    sig_kernel<<<N_B, 256>>>(batch, conv_w, conv_b);

    dim3 grid(NPAD / 128, M_TOT / 128);   // (7, 512); x fast -> A tiles reuse in L2
    gemm_mma<<<grid, 256>>>(lin_b, out);
}